// round 1
// baseline (speedup 1.0000x reference)
#include <cuda_runtime.h>

#define E 1280
#define KDIM 588
#define KP 592
#define NPATCH 6016
#define MAXSEQ 2048
#define NB 5

// ---------------- scratch (device globals: no allocation allowed) ----------
__device__ float g_patches[NPATCH * KP];   // im2col, K padded to 592 with zeros
__device__ float g_wt[KP * E];             // conv_w transposed to [K][E], padded
__device__ float g_x[NPATCH * E];          // pre-LN GEMM result

// ---------------- static image / packing metadata --------------------------
__constant__ int c_H[6]   = {448, 448, 336, 224, 560, 336};
__constant__ int c_W[6]   = {448, 672, 336, 448, 560, 448};
__constant__ int c_h[6]   = {32, 32, 24, 16, 40, 24};
__constant__ int c_w[6]   = {32, 48, 24, 32, 40, 32};
__constant__ int c_off[7] = {0, 1024, 2560, 3136, 3648, 5248, 6016};
__constant__ int c_bi[6]  = {0, 1, 2, 2, 3, 4};
__constant__ int c_s[6]   = {0, 0, 0, 576, 0, 0};

// mask coverage intervals per batch: [lo0,hi0), [lo1,hi1) (second may be empty)
__constant__ int c_iv[5][4] = {
    {0, 1024, 0, 0},
    {0, 1536, 0, 0},
    {0, 576, 576, 1088},
    {0, 1600, 0, 0},
    {0, 768, 0, 0}};

struct Imgs { const float* p[6]; };

// ---------------- im2col: (6016, 592) -------------------------------------
__global__ __launch_bounds__(256) void im2col_kernel(Imgs imgs) {
    int idx = blockIdx.x * 256 + threadIdx.x;
    if (idx >= NPATCH * KP) return;
    int gp = idx / KP;
    int f  = idx - gp * KP;
    int im = 0;
#pragma unroll
    for (int i = 1; i < 6; i++) if (gp >= c_off[i]) im = i;
    int p  = gp - c_off[im];
    int w  = c_w[im], W = c_W[im], H = c_H[im];
    int py = p / w, px = p - py * w;
    float v = 0.f;
    if (f < KDIM) {
        int ch  = f / 196;
        int rem = f - ch * 196;
        int r   = rem / 14;
        int cc  = rem - r * 14;
        v = imgs.p[im][((ch * H) + py * 14 + r) * W + px * 14 + cc];
    }
    g_patches[gp * KP + f] = v;
}

// ---------------- transpose conv_w to [K][E], zero-pad K -------------------
__global__ __launch_bounds__(256) void wt_kernel(const float* __restrict__ conv_w) {
    int idx = blockIdx.x * 256 + threadIdx.x;
    if (idx >= E * KP) return;
    int n = idx / KP;
    int k = idx - n * KP;
    g_wt[k * E + n] = (k < KDIM) ? conv_w[n * KDIM + k] : 0.f;
}

// ---------------- fp32 SGEMM: g_x[6016,1280] = g_patches @ g_wt ------------
// 128x128 tile, BK=8, 256 threads, 8x8 per thread
__global__ __launch_bounds__(256, 2) void gemm_kernel() {
    __shared__ float As[8][128];
    __shared__ float Bs[8][128];
    int tid = threadIdx.x;
    int tx = tid & 15, ty = tid >> 4;
    int row0 = blockIdx.y * 128, col0 = blockIdx.x * 128;

    float acc[8][8];
#pragma unroll
    for (int i = 0; i < 8; i++)
#pragma unroll
        for (int j = 0; j < 8; j++) acc[i][j] = 0.f;

    int a_row = tid >> 1, a_k = (tid & 1) * 4;
    int b_k = tid >> 5, b_n = (tid & 31) * 4;
    const float* Aptr = g_patches + (size_t)(row0 + a_row) * KP + a_k;
    const float* Bptr = g_wt + (size_t)b_k * E + col0 + b_n;

    for (int kt = 0; kt < 74; kt++) {  // 74*8 = 592 = KP
        float4 av = *(const float4*)(Aptr + kt * 8);
        float4 bv = *(const float4*)(Bptr + (size_t)kt * 8 * E);
        __syncthreads();
        As[a_k + 0][a_row] = av.x;
        As[a_k + 1][a_row] = av.y;
        As[a_k + 2][a_row] = av.z;
        As[a_k + 3][a_row] = av.w;
        *(float4*)&Bs[b_k][b_n] = bv;
        __syncthreads();
#pragma unroll
        for (int k = 0; k < 8; k++) {
            float a[8], b[8];
            *(float4*)(a)     = *(float4*)&As[k][ty * 8];
            *(float4*)(a + 4) = *(float4*)&As[k][ty * 8 + 4];
            *(float4*)(b)     = *(float4*)&Bs[k][tx * 8];
            *(float4*)(b + 4) = *(float4*)&Bs[k][tx * 8 + 4];
#pragma unroll
            for (int i = 0; i < 8; i++)
#pragma unroll
                for (int j = 0; j < 8; j++) acc[i][j] += a[i] * b[j];
        }
    }

#pragma unroll
    for (int i = 0; i < 8; i++) {
        int row = row0 + ty * 8 + i;
        float* o = g_x + (size_t)row * E + col0 + tx * 8;
        *(float4*)(o)     = make_float4(acc[i][0], acc[i][1], acc[i][2], acc[i][3]);
        *(float4*)(o + 4) = make_float4(acc[i][4], acc[i][5], acc[i][6], acc[i][7]);
    }
}

// ---------------- pos-embed interp + bias + LayerNorm + scatter ------------
__global__ __launch_bounds__(256) void ln_kernel(const float* __restrict__ conv_b,
                                                 const float* __restrict__ pos_table,
                                                 const float* __restrict__ ln_w,
                                                 const float* __restrict__ ln_b,
                                                 float* __restrict__ out) {
    int gp = blockIdx.x;
    int im = 0;
#pragma unroll
    for (int i = 1; i < 6; i++) if (gp >= c_off[i]) im = i;
    int p = gp - c_off[im];
    int h = c_h[im], w = c_w[im];
    int py = p / w, px = p - py * w;

    float cy = (py + 0.5f) * (32.0f / (float)h) - 0.5f;
    cy = fminf(fmaxf(cy, 0.f), 31.f);
    float cx = (px + 0.5f) * (32.0f / (float)w) - 0.5f;
    cx = fminf(fmaxf(cx, 0.f), 31.f);
    int y0 = (int)cy; int y1 = min(y0 + 1, 31); float fy = cy - (float)y0;
    int x0 = (int)cx; int x1 = min(x0 + 1, 31); float fx = cx - (float)x0;

    const float* T00 = pos_table + (size_t)(1 + y0 * 32 + x0) * E;
    const float* T01 = pos_table + (size_t)(1 + y0 * 32 + x1) * E;
    const float* T10 = pos_table + (size_t)(1 + y1 * 32 + x0) * E;
    const float* T11 = pos_table + (size_t)(1 + y1 * 32 + x1) * E;
    float w00 = (1.f - fy) * (1.f - fx), w01 = (1.f - fy) * fx;
    float w10 = fy * (1.f - fx), w11 = fy * fx;

    int tid = threadIdx.x;
    float y[5];
    float s = 0.f, ss = 0.f;
#pragma unroll
    for (int i = 0; i < 5; i++) {
        int f = tid + i * 256;
        float v = g_x[(size_t)gp * E + f] + conv_b[f]
                + w00 * T00[f] + w01 * T01[f] + w10 * T10[f] + w11 * T11[f];
        y[i] = v;
        s += v;
        ss += v * v;
    }

    __shared__ float rs[8], rss[8];
#pragma unroll
    for (int o = 16; o > 0; o >>= 1) {
        s  += __shfl_xor_sync(0xffffffffu, s, o);
        ss += __shfl_xor_sync(0xffffffffu, ss, o);
    }
    if ((tid & 31) == 0) { rs[tid >> 5] = s; rss[tid >> 5] = ss; }
    __syncthreads();
    __shared__ float fm, finv;
    if (tid == 0) {
        float S = 0.f, SS = 0.f;
#pragma unroll
        for (int i = 0; i < 8; i++) { S += rs[i]; SS += rss[i]; }
        float m = S / (float)E;
        fm = m;
        finv = rsqrtf(SS / (float)E - m * m + 1e-5f);
    }
    __syncthreads();
    float m = fm, inv = finv;

    int row = c_bi[im] * MAXSEQ + c_s[im] + p;
    float* o = out + (size_t)row * E;
#pragma unroll
    for (int i = 0; i < 5; i++) {
        int f = tid + i * 256;
        o[f] = (y[i] - m) * inv * ln_w[f] + ln_b[f];
    }
}

// ---------------- zero emb region ------------------------------------------
__global__ __launch_bounds__(256) void zero_kernel(float4* __restrict__ out) {
    int idx = blockIdx.x * 256 + threadIdx.x;
    if (idx < NB * MAXSEQ * E / 4) out[idx] = make_float4(0.f, 0.f, 0.f, 0.f);
}

// ---------------- mask fill -------------------------------------------------
__global__ __launch_bounds__(256) void mask_kernel(float4* __restrict__ mask) {
    int idx = blockIdx.x * 256 + threadIdx.x;
    const int per_batch = MAXSEQ * MAXSEQ / 4;  // 1048576
    if (idx >= NB * per_batch) return;
    int b   = idx / per_batch;
    int rem = idx - b * per_batch;
    int r   = rem / (MAXSEQ / 4);
    int c   = (rem - r * (MAXSEQ / 4)) * 4;  // boundaries all multiples of 4
    const int* iv = c_iv[b];
    float v = 0.f;
    if (r >= iv[0] && r < iv[1]) {
        if (c >= iv[0] && c < iv[1]) v = 1.f;
    } else if (iv[3] > iv[2] && r >= iv[2] && r < iv[3]) {
        if (c >= iv[2] && c < iv[3]) v = 1.f;
    }
    mask[idx] = make_float4(v, v, v, v);
}

// ---------------- launch ----------------------------------------------------
extern "C" void kernel_launch(void* const* d_in, const int* in_sizes, int n_in,
                              void* d_out, int out_size) {
    Imgs imgs;
    for (int i = 0; i < 6; i++) imgs.p[i] = (const float*)d_in[i];
    const float* conv_w = (const float*)d_in[6];
    const float* conv_b = (const float*)d_in[7];
    const float* pos    = (const float*)d_in[8];
    const float* ln_w   = (const float*)d_in[9];
    const float* ln_b   = (const float*)d_in[10];

    float* out  = (float*)d_out;
    float* mask = out + (size_t)NB * MAXSEQ * E;  // 13,107,200 floats in

    im2col_kernel<<<(NPATCH * KP + 255) / 256, 256>>>(imgs);
    wt_kernel<<<(E * KP + 255) / 256, 256>>>(conv_w);
    zero_kernel<<<(NB * MAXSEQ * E / 4 + 255) / 256, 256>>>((float4*)out);
    mask_kernel<<<(NB * MAXSEQ * MAXSEQ / 4 + 255) / 256, 256>>>((float4*)mask);
    gemm_kernel<<<dim3(E / 128, NPATCH / 128), 256>>>();
    ln_kernel<<<NPATCH, 256>>>(conv_b, pos, ln_w, ln_b, out);
}

// round 3
// speedup vs baseline: 1.7352x; 1.7352x over previous
#include <cuda_runtime.h>
#include <cuda_bf16.h>
#include <cstdint>

#define E 1280
#define KDIM 588
#define KP 640            // padded K
#define NPATCH 6016
#define MAXSEQ 2048
#define NB 5

// ---------------- scratch (device globals: no allocation allowed) ----------
__device__ __nv_bfloat16 g_a_hi[NPATCH * KP];
__device__ __nv_bfloat16 g_a_lo[NPATCH * KP];
__device__ __nv_bfloat16 g_b_hi[E * KP];
__device__ __nv_bfloat16 g_b_lo[E * KP];
__device__ float g_x[NPATCH * E];          // pre-LN GEMM result

// ---------------- static image / packing metadata --------------------------
__constant__ int c_H[6]   = {448, 448, 336, 224, 560, 336};
__constant__ int c_W[6]   = {448, 672, 336, 448, 560, 448};
__constant__ int c_h[6]   = {32, 32, 24, 16, 40, 24};
__constant__ int c_w[6]   = {32, 48, 24, 32, 40, 32};
__constant__ int c_off[7] = {0, 1024, 2560, 3136, 3648, 5248, 6016};
__constant__ int c_bi[6]  = {0, 1, 2, 2, 3, 4};
__constant__ int c_s[6]   = {0, 0, 0, 576, 0, 0};
__constant__ int c_cov[5] = {1024, 1536, 1088, 1600, 768};  // covered rows per batch
__constant__ int c_iv[5][4] = {
    {0, 1024, 0, 0},
    {0, 1536, 0, 0},
    {0, 576, 576, 1088},
    {0, 1600, 0, 0},
    {0, 768, 0, 0}};

struct Imgs { const float* p[6]; };

// ---------------- PTX helpers ----------------------------------------------
__device__ __forceinline__ uint32_t smem_u32(const void* p) {
    uint32_t a;
    asm("{ .reg .u64 t; cvta.to.shared.u64 t, %1; cvt.u32.u64 %0, t; }"
        : "=r"(a) : "l"(p));
    return a;
}

#define CP16(dst, src) \
    asm volatile("cp.async.cg.shared.global [%0], [%1], 16;" :: "r"(dst), "l"(src))
#define CP_COMMIT() asm volatile("cp.async.commit_group;" ::: "memory")
#define CP_WAIT(n)  asm volatile("cp.async.wait_group %0;" :: "n"(n) : "memory")

#define LDSM4(r, addr)                                                          \
    asm volatile("ldmatrix.sync.aligned.m8n8.x4.shared.b16 {%0,%1,%2,%3}, [%4];" \
        : "=r"((r)[0]), "=r"((r)[1]), "=r"((r)[2]), "=r"((r)[3]) : "r"(addr))
#define LDSM2(r, addr)                                                          \
    asm volatile("ldmatrix.sync.aligned.m8n8.x2.shared.b16 {%0,%1}, [%2];"      \
        : "=r"((r)[0]), "=r"((r)[1]) : "r"(addr))

#define MMA(d, a, b)                                                            \
    asm volatile("mma.sync.aligned.m16n8k16.row.col.f32.bf16.bf16.f32 "         \
        "{%0,%1,%2,%3}, {%4,%5,%6,%7}, {%8,%9}, {%0,%1,%2,%3};"                 \
        : "+f"((d)[0]), "+f"((d)[1]), "+f"((d)[2]), "+f"((d)[3])                \
        : "r"((a)[0]), "r"((a)[1]), "r"((a)[2]), "r"((a)[3]),                   \
          "r"((b)[0]), "r"((b)[1]))

// ---------------- im2col -> bf16 hi/lo ------------------------------------
__global__ __launch_bounds__(256) void a_conv_kernel(Imgs imgs) {
    int idx = blockIdx.x * 256 + threadIdx.x;
    if (idx >= NPATCH * KP) return;
    int gp = idx / KP;
    int f  = idx - gp * KP;
    int im = 0;
#pragma unroll
    for (int i = 1; i < 6; i++) if (gp >= c_off[i]) im = i;
    int p  = gp - c_off[im];
    int w  = c_w[im], W = c_W[im], H = c_H[im];
    int py = p / w, px = p - py * w;
    float v = 0.f;
    if (f < KDIM) {
        int ch  = f / 196;
        int rem = f - ch * 196;
        int r   = rem / 14;
        int cc  = rem - r * 14;
        v = imgs.p[im][((ch * H) + py * 14 + r) * W + px * 14 + cc];
    }
    __nv_bfloat16 hi = __float2bfloat16(v);
    g_a_hi[idx] = hi;
    g_a_lo[idx] = __float2bfloat16(v - __bfloat162float(hi));
}

// ---------------- conv_w -> bf16 hi/lo [N=1280][K=640] ---------------------
__global__ __launch_bounds__(256) void b_conv_kernel(const float* __restrict__ conv_w) {
    int idx = blockIdx.x * 256 + threadIdx.x;
    if (idx >= E * KP) return;
    int n = idx / KP;
    int k = idx - n * KP;
    float v = (k < KDIM) ? conv_w[n * KDIM + k] : 0.f;
    __nv_bfloat16 hi = __float2bfloat16(v);
    g_b_hi[idx] = hi;
    g_b_lo[idx] = __float2bfloat16(v - __bfloat162float(hi));
}

// ---------------- bf16-split HMMA GEMM -------------------------------------
// CTA 128x128, BK=32, 256 threads (8 warps, 2x4), warp tile 64x32.
// SMEM rows padded to 40 bf16 (80B) for conflict-free ldmatrix.
#define KROW 40
#define TILE_B (128 * KROW * 2)      // 10240 bytes per (array) tile
#define STAGE_B (4 * TILE_B)         // Ahi, Alo, Bhi, Blo
#define SMEM_TOTAL (2 * STAGE_B)     // double buffer = 81920

__global__ __launch_bounds__(256, 2) void gemm_mma() {
    extern __shared__ __align__(128) char smem[];
    uint32_t sbase = smem_u32(smem);
    int tid  = threadIdx.x;
    int lane = tid & 31;
    int wid  = tid >> 5;
    int wm = wid >> 2, wn = wid & 3;
    int bm = blockIdx.y, bn = blockIdx.x;

    const __nv_bfloat16* gA[2] = {g_a_hi + (size_t)bm * 128 * KP,
                                  g_a_lo + (size_t)bm * 128 * KP};
    const __nv_bfloat16* gB[2] = {g_b_hi + (size_t)bn * 128 * KP,
                                  g_b_lo + (size_t)bn * 128 * KP};

    float acc[4][4][4];
#pragma unroll
    for (int i = 0; i < 4; i++)
#pragma unroll
        for (int j = 0; j < 4; j++)
#pragma unroll
            for (int q = 0; q < 4; q++) acc[i][j][q] = 0.f;

    // async load of one stage: 2048 16B chunks
    auto load_stage = [&](int buf, int k0) {
        uint32_t st = sbase + buf * STAGE_B;
#pragma unroll
        for (int i = 0; i < 8; i++) {
            int c   = tid + i * 256;
            int arr = c >> 9;          // 0:Ahi 1:Alo 2:Bhi 3:Blo
            int rem = c & 511;
            int row = rem >> 2;
            int cg  = rem & 3;
            const __nv_bfloat16* g = (arr < 2) ? gA[arr] : gB[arr - 2];
            const __nv_bfloat16* src = g + (size_t)row * KP + k0 + cg * 8;
            uint32_t dst = st + arr * TILE_B + row * (KROW * 2) + cg * 16;
            CP16(dst, src);
        }
        CP_COMMIT();
    };

    load_stage(0, 0);

    // per-lane ldmatrix address offsets
    int a_row = wm * 64 + (lane & 15);
    int a_cg  = (lane >> 4);                 // 0/1 -> col +0/+8
    int b_row = wn * 32 + (lane & 7);
    int b_cg  = (lane >> 3) & 1;

    for (int it = 0; it < 20; it++) {
        if (it + 1 < 20) load_stage((it + 1) & 1, (it + 1) * 32);
        if (it + 1 < 20) { CP_WAIT(1); } else { CP_WAIT(0); }
        __syncthreads();

        uint32_t st  = sbase + (it & 1) * STAGE_B;
        uint32_t aHi = st;
        uint32_t aLo = st + TILE_B;
        uint32_t bHi = st + 2 * TILE_B;
        uint32_t bLo = st + 3 * TILE_B;

#pragma unroll
        for (int ks = 0; ks < 2; ks++) {
            int acol = ks * 16 + a_cg * 8;
            int bcol = ks * 16 + b_cg * 8;
            uint32_t ahi[4][4], alo[4][4], bhi[4][2], blo[4][2];
#pragma unroll
            for (int mt = 0; mt < 4; mt++) {
                uint32_t off = (a_row + mt * 16) * (KROW * 2) + acol * 2;
                LDSM4(ahi[mt], aHi + off);
                LDSM4(alo[mt], aLo + off);
            }
#pragma unroll
            for (int nt = 0; nt < 4; nt++) {
                uint32_t off = (b_row + nt * 8) * (KROW * 2) + bcol * 2;
                LDSM2(bhi[nt], bHi + off);
                LDSM2(blo[nt], bLo + off);
            }
#pragma unroll
            for (int mt = 0; mt < 4; mt++)
#pragma unroll
                for (int nt = 0; nt < 4; nt++) MMA(acc[mt][nt], ahi[mt], bhi[nt]);
#pragma unroll
            for (int mt = 0; mt < 4; mt++)
#pragma unroll
                for (int nt = 0; nt < 4; nt++) MMA(acc[mt][nt], ahi[mt], blo[nt]);
#pragma unroll
            for (int mt = 0; mt < 4; mt++)
#pragma unroll
                for (int nt = 0; nt < 4; nt++) MMA(acc[mt][nt], alo[mt], bhi[nt]);
        }
        __syncthreads();
    }

    // epilogue
    int g = lane >> 2, t = lane & 3;
    int row0 = bm * 128 + wm * 64;
    int col0 = bn * 128 + wn * 32;
#pragma unroll
    for (int mt = 0; mt < 4; mt++) {
#pragma unroll
        for (int nt = 0; nt < 4; nt++) {
            float* p = g_x + (size_t)(row0 + mt * 16 + g) * E + col0 + nt * 8 + t * 2;
            *(float2*)p           = make_float2(acc[mt][nt][0], acc[mt][nt][1]);
            *(float2*)(p + 8 * E) = make_float2(acc[mt][nt][2], acc[mt][nt][3]);
        }
    }
}

// ---------------- pos-embed interp + bias + LayerNorm + scatter ------------
__global__ __launch_bounds__(256) void ln_kernel(const float* __restrict__ conv_b,
                                                 const float* __restrict__ pos_table,
                                                 const float* __restrict__ ln_w,
                                                 const float* __restrict__ ln_b,
                                                 float* __restrict__ out) {
    int gp = blockIdx.x;
    int im = 0;
#pragma unroll
    for (int i = 1; i < 6; i++) if (gp >= c_off[i]) im = i;
    int p = gp - c_off[im];
    int h = c_h[im], w = c_w[im];
    int py = p / w, px = p - py * w;

    float cy = (py + 0.5f) * (32.0f / (float)h) - 0.5f;
    cy = fminf(fmaxf(cy, 0.f), 31.f);
    float cx = (px + 0.5f) * (32.0f / (float)w) - 0.5f;
    cx = fminf(fmaxf(cx, 0.f), 31.f);
    int y0 = (int)cy; int y1 = min(y0 + 1, 31); float fy = cy - (float)y0;
    int x0 = (int)cx; int x1 = min(x0 + 1, 31); float fx = cx - (float)x0;

    const float* T00 = pos_table + (size_t)(1 + y0 * 32 + x0) * E;
    const float* T01 = pos_table + (size_t)(1 + y0 * 32 + x1) * E;
    const float* T10 = pos_table + (size_t)(1 + y1 * 32 + x0) * E;
    const float* T11 = pos_table + (size_t)(1 + y1 * 32 + x1) * E;
    float w00 = (1.f - fy) * (1.f - fx), w01 = (1.f - fy) * fx;
    float w10 = fy * (1.f - fx), w11 = fy * fx;

    int tid = threadIdx.x;
    float y[5];
    float s = 0.f, ss = 0.f;
#pragma unroll
    for (int i = 0; i < 5; i++) {
        int f = tid + i * 256;
        float v = g_x[(size_t)gp * E + f] + conv_b[f]
                + w00 * T00[f] + w01 * T01[f] + w10 * T10[f] + w11 * T11[f];
        y[i] = v;
        s += v;
        ss += v * v;
    }

    __shared__ float rs[8], rss[8];
#pragma unroll
    for (int o = 16; o > 0; o >>= 1) {
        s  += __shfl_xor_sync(0xffffffffu, s, o);
        ss += __shfl_xor_sync(0xffffffffu, ss, o);
    }
    if ((tid & 31) == 0) { rs[tid >> 5] = s; rss[tid >> 5] = ss; }
    __syncthreads();
    __shared__ float fm, finv;
    if (tid == 0) {
        float S = 0.f, SS = 0.f;
#pragma unroll
        for (int i = 0; i < 8; i++) { S += rs[i]; SS += rss[i]; }
        float m = S / (float)E;
        fm = m;
        finv = rsqrtf(SS / (float)E - m * m + 1e-5f);
    }
    __syncthreads();
    float m = fm, inv = finv;

    int row = c_bi[im] * MAXSEQ + c_s[im] + p;
    float* o = out + (size_t)row * E;
#pragma unroll
    for (int i = 0; i < 5; i++) {
        int f = tid + i * 256;
        o[f] = (y[i] - m) * inv * ln_w[f] + ln_b[f];
    }
}

// ---------------- zero uncovered emb rows ----------------------------------
__global__ __launch_bounds__(256) void zero_kernel(float4* __restrict__ out) {
    int idx = blockIdx.x * 256 + threadIdx.x;
    if (idx >= NB * MAXSEQ * E / 4) return;
    int row = idx / (E / 4);
    int b = row >> 11;
    if ((row & 2047) < c_cov[b]) return;  // covered by ln_kernel
    out[idx] = make_float4(0.f, 0.f, 0.f, 0.f);
}

// ---------------- mask fill: one block per (batch,row) ---------------------
__global__ __launch_bounds__(256) void mask_kernel(float4* __restrict__ mask) {
    int b = blockIdx.x >> 11;
    int r = blockIdx.x & 2047;
    const int* iv = c_iv[b];
    int lo = -1, hi = -1;
    if (r >= iv[0] && r < iv[1]) { lo = iv[0]; hi = iv[1]; }
    else if (iv[3] > iv[2] && r >= iv[2] && r < iv[3]) { lo = iv[2]; hi = iv[3]; }
    float4* row = mask + ((size_t)blockIdx.x * MAXSEQ) / 4;
    int tid = threadIdx.x;
    int c0 = tid * 8;  // 8 floats per thread (boundaries are multiples of 16)
    float v = (c0 >= lo && c0 < hi) ? 1.f : 0.f;
    float4 vv = make_float4(v, v, v, v);
    row[tid * 2]     = vv;
    row[tid * 2 + 1] = vv;
}

// ---------------- launch ----------------------------------------------------
extern "C" void kernel_launch(void* const* d_in, const int* in_sizes, int n_in,
                              void* d_out, int out_size) {
    Imgs imgs;
    for (int i = 0; i < 6; i++) imgs.p[i] = (const float*)d_in[i];
    const float* conv_w = (const float*)d_in[6];
    const float* conv_b = (const float*)d_in[7];
    const float* pos    = (const float*)d_in[8];
    const float* ln_w   = (const float*)d_in[9];
    const float* ln_b   = (const float*)d_in[10];

    float* out  = (float*)d_out;
    float* mask = out + (size_t)NB * MAXSEQ * E;

    static int smem_set = 0;
    if (!smem_set) {
        cudaFuncSetAttribute(gemm_mma, cudaFuncAttributeMaxDynamicSharedMemorySize,
                             SMEM_TOTAL);
        smem_set = 1;
    }

    a_conv_kernel<<<(NPATCH * KP + 255) / 256, 256>>>(imgs);
    b_conv_kernel<<<(E * KP + 255) / 256, 256>>>(conv_w);
    zero_kernel<<<(NB * MAXSEQ * E / 4 + 255) / 256, 256>>>((float4*)out);
    mask_kernel<<<NB * MAXSEQ, 256>>>((float4*)mask);
    gemm_mma<<<dim3(E / 128, NPATCH / 128), 256, SMEM_TOTAL>>>();
    ln_kernel<<<NPATCH, 256>>>(conv_b, pos, ln_w, ln_b, out);
}

// round 4
// speedup vs baseline: 1.8936x; 1.0913x over previous
#include <cuda_runtime.h>
#include <cuda_bf16.h>
#include <cstdint>

#define E 1280
#define KDIM 588
#define KP 608            // padded K = 19 * 32
#define NPATCH 6016
#define MAXSEQ 2048
#define NB 5

// ---------------- scratch (device globals: no allocation allowed) ----------
__device__ __align__(16) __nv_bfloat16 g_a_hi[NPATCH * KP];
__device__ __align__(16) __nv_bfloat16 g_a_lo[NPATCH * KP];
__device__ __align__(16) __nv_bfloat16 g_b_hi[E * KP];
__device__ __align__(16) __nv_bfloat16 g_b_lo[E * KP];
__device__ __align__(16) float g_x[NPATCH * E];   // pre-LN GEMM result

// ---------------- static image / packing metadata --------------------------
__constant__ int c_H[6]   = {448, 448, 336, 224, 560, 336};
__constant__ int c_W[6]   = {448, 672, 336, 448, 560, 448};
__constant__ int c_h[6]   = {32, 32, 24, 16, 40, 24};
__constant__ int c_w[6]   = {32, 48, 24, 32, 40, 32};
__constant__ int c_off[7] = {0, 1024, 2560, 3136, 3648, 5248, 6016};
__constant__ int c_bi[6]  = {0, 1, 2, 2, 3, 4};
__constant__ int c_s[6]   = {0, 0, 0, 576, 0, 0};
__constant__ int c_cov[5] = {1024, 1536, 1088, 1600, 768};  // covered rows per batch
__constant__ int c_iv[5][4] = {
    {0, 1024, 0, 0},
    {0, 1536, 0, 0},
    {0, 576, 576, 1088},
    {0, 1600, 0, 0},
    {0, 768, 0, 0}};

struct Imgs { const float* p[6]; };

// ---------------- PTX helpers ----------------------------------------------
__device__ __forceinline__ uint32_t smem_u32(const void* p) {
    uint32_t a;
    asm("{ .reg .u64 t; cvta.to.shared.u64 t, %1; cvt.u32.u64 %0, t; }"
        : "=r"(a) : "l"(p));
    return a;
}

#define CP16(dst, src) \
    asm volatile("cp.async.cg.shared.global [%0], [%1], 16;" :: "r"(dst), "l"(src))
#define CP_COMMIT() asm volatile("cp.async.commit_group;" ::: "memory")
#define CP_WAIT(n)  asm volatile("cp.async.wait_group %0;" :: "n"(n) : "memory")

#define LDSM4(r, addr)                                                          \
    asm volatile("ldmatrix.sync.aligned.m8n8.x4.shared.b16 {%0,%1,%2,%3}, [%4];" \
        : "=r"((r)[0]), "=r"((r)[1]), "=r"((r)[2]), "=r"((r)[3]) : "r"(addr))
#define LDSM2(r, addr)                                                          \
    asm volatile("ldmatrix.sync.aligned.m8n8.x2.shared.b16 {%0,%1}, [%2];"      \
        : "=r"((r)[0]), "=r"((r)[1]) : "r"(addr))

#define MMA(d, a, b)                                                            \
    asm volatile("mma.sync.aligned.m16n8k16.row.col.f32.bf16.bf16.f32 "         \
        "{%0,%1,%2,%3}, {%4,%5,%6,%7}, {%8,%9}, {%0,%1,%2,%3};"                 \
        : "+f"((d)[0]), "+f"((d)[1]), "+f"((d)[2]), "+f"((d)[3])                \
        : "r"((a)[0]), "r"((a)[1]), "r"((a)[2]), "r"((a)[3]),                   \
          "r"((b)[0]), "r"((b)[1]))

// ---------------- im2col -> bf16 hi/lo ------------------------------------
__global__ __launch_bounds__(256) void a_conv_kernel(Imgs imgs) {
    int idx = blockIdx.x * 256 + threadIdx.x;
    if (idx >= NPATCH * KP) return;
    int gp = idx / KP;
    int f  = idx - gp * KP;
    int im = 0;
#pragma unroll
    for (int i = 1; i < 6; i++) if (gp >= c_off[i]) im = i;
    int p  = gp - c_off[im];
    int w  = c_w[im], W = c_W[im], H = c_H[im];
    int py = p / w, px = p - py * w;
    float v = 0.f;
    if (f < KDIM) {
        int ch  = f / 196;
        int rem = f - ch * 196;
        int r   = rem / 14;
        int cc  = rem - r * 14;
        v = imgs.p[im][((ch * H) + py * 14 + r) * W + px * 14 + cc];
    }
    __nv_bfloat16 hi = __float2bfloat16(v);
    g_a_hi[idx] = hi;
    g_a_lo[idx] = __float2bfloat16(v - __bfloat162float(hi));
}

// ---------------- conv_w -> bf16 hi/lo [N=1280][K=608] ---------------------
__global__ __launch_bounds__(256) void b_conv_kernel(const float* __restrict__ conv_w) {
    int idx = blockIdx.x * 256 + threadIdx.x;
    if (idx >= E * KP) return;
    int n = idx / KP;
    int k = idx - n * KP;
    float v = (k < KDIM) ? conv_w[n * KDIM + k] : 0.f;
    __nv_bfloat16 hi = __float2bfloat16(v);
    g_b_hi[idx] = hi;
    g_b_lo[idx] = __float2bfloat16(v - __bfloat162float(hi));
}

// ---------------- bf16-split HMMA GEMM -------------------------------------
// CTA 128x128, BK=32, 256 threads (8 warps, 2x4), warp tile 64x32.
// SMEM rows padded to 40 bf16 (80B) for conflict-free ldmatrix.
#define KROW 40
#define TILE_B (128 * KROW * 2)      // 10240 bytes per (array) tile
#define STAGE_B (4 * TILE_B)         // Ahi, Alo, Bhi, Blo
#define SMEM_TOTAL (2 * STAGE_B)     // double buffer = 81920
#define NITER 19                     // 19 * 32 = 608

__global__ __launch_bounds__(256, 2) void gemm_mma() {
    extern __shared__ __align__(128) char smem[];
    uint32_t sbase = smem_u32(smem);
    int tid  = threadIdx.x;
    int lane = tid & 31;
    int wid  = tid >> 5;
    int wm = wid >> 2, wn = wid & 3;
    int bm = blockIdx.y, bn = blockIdx.x;

    const __nv_bfloat16* gA[2] = {g_a_hi + (size_t)bm * 128 * KP,
                                  g_a_lo + (size_t)bm * 128 * KP};
    const __nv_bfloat16* gB[2] = {g_b_hi + (size_t)bn * 128 * KP,
                                  g_b_lo + (size_t)bn * 128 * KP};

    float acc[4][4][4];
#pragma unroll
    for (int i = 0; i < 4; i++)
#pragma unroll
        for (int j = 0; j < 4; j++)
#pragma unroll
            for (int q = 0; q < 4; q++) acc[i][j][q] = 0.f;

    // async load of one stage: 2048 16B chunks
    auto load_stage = [&](int buf, int k0) {
        uint32_t st = sbase + buf * STAGE_B;
#pragma unroll
        for (int i = 0; i < 8; i++) {
            int c   = tid + i * 256;
            int arr = c >> 9;          // 0:Ahi 1:Alo 2:Bhi 3:Blo
            int rem = c & 511;
            int row = rem >> 2;
            int cg  = rem & 3;
            const __nv_bfloat16* g = (arr < 2) ? gA[arr] : gB[arr - 2];
            const __nv_bfloat16* src = g + (size_t)row * KP + k0 + cg * 8;
            uint32_t dst = st + arr * TILE_B + row * (KROW * 2) + cg * 16;
            CP16(dst, src);
        }
        CP_COMMIT();
    };

    load_stage(0, 0);

    // per-lane ldmatrix address offsets
    int a_row = wm * 64 + (lane & 15);
    int a_cg  = (lane >> 4);                 // 0/1 -> col +0/+8
    int b_row = wn * 32 + (lane & 7);
    int b_cg  = (lane >> 3) & 1;

    for (int it = 0; it < NITER; it++) {
        if (it + 1 < NITER) load_stage((it + 1) & 1, (it + 1) * 32);
        if (it + 1 < NITER) { CP_WAIT(1); } else { CP_WAIT(0); }
        __syncthreads();

        uint32_t st  = sbase + (it & 1) * STAGE_B;
        uint32_t aHi = st;
        uint32_t aLo = st + TILE_B;
        uint32_t bHi = st + 2 * TILE_B;
        uint32_t bLo = st + 3 * TILE_B;

#pragma unroll
        for (int ks = 0; ks < 2; ks++) {
            int acol = ks * 16 + a_cg * 8;
            int bcol = ks * 16 + b_cg * 8;
            uint32_t ar[4][4], br[4][2];
            uint32_t aoff = a_row * (KROW * 2) + acol * 2;
            uint32_t boff = b_row * (KROW * 2) + bcol * 2;

            // pass 1: ahi x bhi
#pragma unroll
            for (int nt = 0; nt < 4; nt++)
                LDSM2(br[nt], bHi + boff + nt * 8 * (KROW * 2));
#pragma unroll
            for (int mt = 0; mt < 4; mt++)
                LDSM4(ar[mt], aHi + aoff + mt * 16 * (KROW * 2));
#pragma unroll
            for (int mt = 0; mt < 4; mt++)
#pragma unroll
                for (int nt = 0; nt < 4; nt++) MMA(acc[mt][nt], ar[mt], br[nt]);

            // pass 2: alo x bhi (reuse br)
#pragma unroll
            for (int mt = 0; mt < 4; mt++)
                LDSM4(ar[mt], aLo + aoff + mt * 16 * (KROW * 2));
#pragma unroll
            for (int mt = 0; mt < 4; mt++)
#pragma unroll
                for (int nt = 0; nt < 4; nt++) MMA(acc[mt][nt], ar[mt], br[nt]);

            // pass 3: ahi x blo
#pragma unroll
            for (int nt = 0; nt < 4; nt++)
                LDSM2(br[nt], bLo + boff + nt * 8 * (KROW * 2));
#pragma unroll
            for (int mt = 0; mt < 4; mt++)
                LDSM4(ar[mt], aHi + aoff + mt * 16 * (KROW * 2));
#pragma unroll
            for (int mt = 0; mt < 4; mt++)
#pragma unroll
                for (int nt = 0; nt < 4; nt++) MMA(acc[mt][nt], ar[mt], br[nt]);
        }
        __syncthreads();
    }

    // epilogue
    int g = lane >> 2, t = lane & 3;
    int row0 = bm * 128 + wm * 64;
    int col0 = bn * 128 + wn * 32;
#pragma unroll
    for (int mt = 0; mt < 4; mt++) {
#pragma unroll
        for (int nt = 0; nt < 4; nt++) {
            float* p = g_x + (size_t)(row0 + mt * 16 + g) * E + col0 + nt * 8 + t * 2;
            *(float2*)p           = make_float2(acc[mt][nt][0], acc[mt][nt][1]);
            *(float2*)(p + 8 * E) = make_float2(acc[mt][nt][2], acc[mt][nt][3]);
        }
    }
}

// ---------------- pos-embed interp + bias + LayerNorm + scatter ------------
__global__ __launch_bounds__(256) void ln_kernel(const float* __restrict__ conv_b,
                                                 const float* __restrict__ pos_table,
                                                 const float* __restrict__ ln_w,
                                                 const float* __restrict__ ln_b,
                                                 float* __restrict__ out) {
    int gp = blockIdx.x;
    int im = 0;
#pragma unroll
    for (int i = 1; i < 6; i++) if (gp >= c_off[i]) im = i;
    int p = gp - c_off[im];
    int h = c_h[im], w = c_w[im];
    int py = p / w, px = p - py * w;

    float cy = (py + 0.5f) * (32.0f / (float)h) - 0.5f;
    cy = fminf(fmaxf(cy, 0.f), 31.f);
    float cx = (px + 0.5f) * (32.0f / (float)w) - 0.5f;
    cx = fminf(fmaxf(cx, 0.f), 31.f);
    int y0 = (int)cy; int y1 = min(y0 + 1, 31); float fy = cy - (float)y0;
    int x0 = (int)cx; int x1 = min(x0 + 1, 31); float fx = cx - (float)x0;

    const float* T00 = pos_table + (size_t)(1 + y0 * 32 + x0) * E;
    const float* T01 = pos_table + (size_t)(1 + y0 * 32 + x1) * E;
    const float* T10 = pos_table + (size_t)(1 + y1 * 32 + x0) * E;
    const float* T11 = pos_table + (size_t)(1 + y1 * 32 + x1) * E;
    float w00 = (1.f - fy) * (1.f - fx), w01 = (1.f - fy) * fx;
    float w10 = fy * (1.f - fx), w11 = fy * fx;

    int tid = threadIdx.x;
    float y[5];
    float s = 0.f, ss = 0.f;
#pragma unroll
    for (int i = 0; i < 5; i++) {
        int f = tid + i * 256;
        float v = g_x[(size_t)gp * E + f] + conv_b[f]
                + w00 * T00[f] + w01 * T01[f] + w10 * T10[f] + w11 * T11[f];
        y[i] = v;
        s += v;
        ss += v * v;
    }

    __shared__ float rs[8], rss[8];
#pragma unroll
    for (int o = 16; o > 0; o >>= 1) {
        s  += __shfl_xor_sync(0xffffffffu, s, o);
        ss += __shfl_xor_sync(0xffffffffu, ss, o);
    }
    if ((tid & 31) == 0) { rs[tid >> 5] = s; rss[tid >> 5] = ss; }
    __syncthreads();
    __shared__ float fm, finv;
    if (tid == 0) {
        float S = 0.f, SS = 0.f;
#pragma unroll
        for (int i = 0; i < 8; i++) { S += rs[i]; SS += rss[i]; }
        float m = S / (float)E;
        fm = m;
        finv = rsqrtf(SS / (float)E - m * m + 1e-5f);
    }
    __syncthreads();
    float m = fm, inv = finv;

    int row = c_bi[im] * MAXSEQ + c_s[im] + p;
    float* o = out + (size_t)row * E;
#pragma unroll
    for (int i = 0; i < 5; i++) {
        int f = tid + i * 256;
        o[f] = (y[i] - m) * inv * ln_w[f] + ln_b[f];
    }
}

// ---------------- zero uncovered emb rows: 4 rows per block ----------------
__global__ __launch_bounds__(256) void zero_kernel(float4* __restrict__ out) {
    int blk = blockIdx.x;              // 0..2559
    int b   = blk >> 9;                // 512 blocks per batch
    int r0  = (blk & 511) * 4;
    if (r0 + 4 <= c_cov[b]) return;    // fully covered by ln_kernel (cov % 4 == 0)
    float4* base = out + ((size_t)(b * MAXSEQ + r0) * E) / 4;
    int tid = threadIdx.x;
    float4 z = make_float4(0.f, 0.f, 0.f, 0.f);
#pragma unroll
    for (int i = 0; i < 5; i++) base[tid + i * 256] = z;   // 1280 float4 = 4 rows
}

// ---------------- mask fill: 4 rows per block, coalesced -------------------
__global__ __launch_bounds__(256) void mask_kernel(float4* __restrict__ mask) {
    int blk = blockIdx.x;              // 0..2559
    int b   = blk >> 9;
    int r0  = (blk & 511) * 4;         // all interval boundaries % 4 == 0
    const int* iv = c_iv[b];
    int lo = -1, hi = -1;
    if (r0 >= iv[0] && r0 < iv[1]) { lo = iv[0]; hi = iv[1]; }
    else if (iv[3] > iv[2] && r0 >= iv[2] && r0 < iv[3]) { lo = iv[2]; hi = iv[3]; }
    float4* base = mask + ((size_t)(b * MAXSEQ + r0) * MAXSEQ) / 4;
    int tid = threadIdx.x;
#pragma unroll
    for (int i = 0; i < 8; i++) {      // 2048 float4 = 4 rows of 512
        int fidx = tid + i * 256;
        int col  = (fidx & 511) * 4;
        float v = (col >= lo && col < hi) ? 1.f : 0.f;
        base[fidx] = make_float4(v, v, v, v);
    }
}

// ---------------- launch ----------------------------------------------------
extern "C" void kernel_launch(void* const* d_in, const int* in_sizes, int n_in,
                              void* d_out, int out_size) {
    Imgs imgs;
    for (int i = 0; i < 6; i++) imgs.p[i] = (const float*)d_in[i];
    const float* conv_w = (const float*)d_in[6];
    const float* conv_b = (const float*)d_in[7];
    const float* pos    = (const float*)d_in[8];
    const float* ln_w   = (const float*)d_in[9];
    const float* ln_b   = (const float*)d_in[10];

    float* out  = (float*)d_out;
    float* mask = out + (size_t)NB * MAXSEQ * E;

    cudaFuncSetAttribute(gemm_mma, cudaFuncAttributeMaxDynamicSharedMemorySize,
                         SMEM_TOTAL);

    a_conv_kernel<<<(NPATCH * KP + 255) / 256, 256>>>(imgs);
    b_conv_kernel<<<(E * KP + 255) / 256, 256>>>(conv_w);
    zero_kernel<<<NB * MAXSEQ / 4, 256>>>((float4*)out);
    mask_kernel<<<NB * MAXSEQ / 4, 256>>>((float4*)mask);
    gemm_mma<<<dim3(E / 128, NPATCH / 128), 256, SMEM_TOTAL>>>();
    ln_kernel<<<NPATCH, 256>>>(conv_b, pos, ln_w, ln_b, out);
}

// round 5
// speedup vs baseline: 2.0016x; 1.0570x over previous
#include <cuda_runtime.h>
#include <cuda_bf16.h>
#include <cstdint>

#define E 1280
#define KDIM 588
#define KP 608            // padded K = 19 * 32
#define NPATCH 6016
#define MAXSEQ 2048
#define NB 5

// ---------------- scratch (device globals: no allocation allowed) ----------
__device__ __align__(16) __nv_bfloat16 g_a_hi[NPATCH * KP];
__device__ __align__(16) __nv_bfloat16 g_a_lo[NPATCH * KP];
__device__ __align__(16) __nv_bfloat16 g_b_hi[E * KP];
__device__ __align__(16) __nv_bfloat16 g_b_lo[E * KP];
__device__ __align__(16) float g_x[NPATCH * E];   // pre-LN GEMM result

// ---------------- static image / packing metadata --------------------------
__constant__ int c_H[6]   = {448, 448, 336, 224, 560, 336};
__constant__ int c_W[6]   = {448, 672, 336, 448, 560, 448};
__constant__ int c_h[6]   = {32, 32, 24, 16, 40, 24};
__constant__ int c_w[6]   = {32, 48, 24, 32, 40, 32};
__constant__ int c_off[7] = {0, 1024, 2560, 3136, 3648, 5248, 6016};
__constant__ int c_bi[6]  = {0, 1, 2, 2, 3, 4};
__constant__ int c_s[6]   = {0, 0, 0, 576, 0, 0};
__constant__ int c_cov[5] = {1024, 1536, 1088, 1600, 768};  // covered rows per batch
__constant__ int c_iv[5][4] = {
    {0, 1024, 0, 0},
    {0, 1536, 0, 0},
    {0, 576, 576, 1088},
    {0, 1600, 0, 0},
    {0, 768, 0, 0}};

struct Imgs { const float* p[6]; };

// ---------------- PTX helpers ----------------------------------------------
__device__ __forceinline__ uint32_t smem_u32(const void* p) {
    uint32_t a;
    asm("{ .reg .u64 t; cvta.to.shared.u64 t, %1; cvt.u32.u64 %0, t; }"
        : "=r"(a) : "l"(p));
    return a;
}

#define CP16(dst, src) \
    asm volatile("cp.async.cg.shared.global [%0], [%1], 16;" :: "r"(dst), "l"(src))
#define CP_COMMIT() asm volatile("cp.async.commit_group;" ::: "memory")
#define CP_WAIT(n)  asm volatile("cp.async.wait_group %0;" :: "n"(n) : "memory")

#define LDSM4(r, addr)                                                          \
    asm volatile("ldmatrix.sync.aligned.m8n8.x4.shared.b16 {%0,%1,%2,%3}, [%4];" \
        : "=r"((r)[0]), "=r"((r)[1]), "=r"((r)[2]), "=r"((r)[3]) : "r"(addr))

#define MMA(d, a, b)                                                            \
    asm volatile("mma.sync.aligned.m16n8k16.row.col.f32.bf16.bf16.f32 "         \
        "{%0,%1,%2,%3}, {%4,%5,%6,%7}, {%8,%9}, {%0,%1,%2,%3};"                 \
        : "+f"((d)[0]), "+f"((d)[1]), "+f"((d)[2]), "+f"((d)[3])                \
        : "r"((a)[0]), "r"((a)[1]), "r"((a)[2]), "r"((a)[3]),                   \
          "r"((b)[0]), "r"((b)[1]))

// ---------------- im2col -> bf16 hi/lo ------------------------------------
__global__ __launch_bounds__(256) void a_conv_kernel(Imgs imgs) {
    int idx = blockIdx.x * 256 + threadIdx.x;
    if (idx >= NPATCH * KP) return;
    int gp = idx / KP;
    int f  = idx - gp * KP;
    int im = 0;
#pragma unroll
    for (int i = 1; i < 6; i++) if (gp >= c_off[i]) im = i;
    int p  = gp - c_off[im];
    int w  = c_w[im], W = c_W[im], H = c_H[im];
    int py = p / w, px = p - py * w;
    float v = 0.f;
    if (f < KDIM) {
        int ch  = f / 196;
        int rem = f - ch * 196;
        int r   = rem / 14;
        int cc  = rem - r * 14;
        v = imgs.p[im][((ch * H) + py * 14 + r) * W + px * 14 + cc];
    }
    __nv_bfloat16 hi = __float2bfloat16(v);
    g_a_hi[idx] = hi;
    g_a_lo[idx] = __float2bfloat16(v - __bfloat162float(hi));
}

// ---------------- conv_w -> bf16 hi/lo [N=1280][K=608] ---------------------
__global__ __launch_bounds__(256) void b_conv_kernel(const float* __restrict__ conv_w) {
    int idx = blockIdx.x * 256 + threadIdx.x;
    if (idx >= E * KP) return;
    int n = idx / KP;
    int k = idx - n * KP;
    float v = (k < KDIM) ? conv_w[n * KDIM + k] : 0.f;
    __nv_bfloat16 hi = __float2bfloat16(v);
    g_b_hi[idx] = hi;
    g_b_lo[idx] = __float2bfloat16(v - __bfloat162float(hi));
}

// ---------------- bf16-split HMMA GEMM -------------------------------------
// CTA 128x128, BK=32, 256 threads (8 warps, 2x4), warp tile 64x32.
// SMEM rows padded to 40 bf16 (80B) for conflict-free ldmatrix.
#define KROW 40
#define TILE_B (128 * KROW * 2)      // 10240 bytes per (array) tile
#define STAGE_B (4 * TILE_B)         // Ahi, Alo, Bhi, Blo
#define SMEM_TOTAL (2 * STAGE_B)     // double buffer = 81920
#define NITER 19                     // 19 * 32 = 608

__global__ __launch_bounds__(256, 2) void gemm_mma() {
    extern __shared__ __align__(128) char smem[];
    uint32_t sbase = smem_u32(smem);
    int tid  = threadIdx.x;
    int lane = tid & 31;
    int wid  = tid >> 5;
    int wm = wid >> 2, wn = wid & 3;
    int bm = blockIdx.y, bn = blockIdx.x;

    const __nv_bfloat16* gA[2] = {g_a_hi + (size_t)bm * 128 * KP,
                                  g_a_lo + (size_t)bm * 128 * KP};
    const __nv_bfloat16* gB[2] = {g_b_hi + (size_t)bn * 128 * KP,
                                  g_b_lo + (size_t)bn * 128 * KP};

    float acc[4][4][4];
#pragma unroll
    for (int i = 0; i < 4; i++)
#pragma unroll
        for (int j = 0; j < 4; j++)
#pragma unroll
            for (int q = 0; q < 4; q++) acc[i][j][q] = 0.f;

    // async load of one stage: 2048 16B chunks
    auto load_stage = [&](int buf, int k0) {
        uint32_t st = sbase + buf * STAGE_B;
#pragma unroll
        for (int i = 0; i < 8; i++) {
            int c   = tid + i * 256;
            int arr = c >> 9;          // 0:Ahi 1:Alo 2:Bhi 3:Blo
            int rem = c & 511;
            int row = rem >> 2;
            int cg  = rem & 3;
            const __nv_bfloat16* g = (arr < 2) ? gA[arr] : gB[arr - 2];
            const __nv_bfloat16* src = g + (size_t)row * KP + k0 + cg * 8;
            uint32_t dst = st + arr * TILE_B + row * (KROW * 2) + cg * 16;
            CP16(dst, src);
        }
        CP_COMMIT();
    };

    load_stage(0, 0);

    // per-lane ldmatrix addressing
    // A (x4, m16k16): lanes 0-15 rows, lane>>4 selects k-half
    int a_row = wm * 64 + (lane & 15);
    int a_cg  = (lane >> 4);
    // B (x4, two n-tiles x k16): see mapping below
    int b_row = wn * 32 + (lane & 7) + ((lane >> 4) << 3);  // +8 for lanes 16-31
    int b_cg  = (lane >> 3) & 1;                            // k-half

    for (int it = 0; it < NITER; it++) {
        if (it + 1 < NITER) load_stage((it + 1) & 1, (it + 1) * 32);
        if (it + 1 < NITER) { CP_WAIT(1); } else { CP_WAIT(0); }
        __syncthreads();

        uint32_t st  = sbase + (it & 1) * STAGE_B;
        uint32_t aHi = st;
        uint32_t aLo = st + TILE_B;
        uint32_t bHi = st + 2 * TILE_B;
        uint32_t bLo = st + 3 * TILE_B;

#pragma unroll
        for (int ks = 0; ks < 2; ks++) {
            uint32_t aoff = a_row * (KROW * 2) + (ks * 16 + a_cg * 8) * 2;
            uint32_t boff = b_row * (KROW * 2) + (ks * 16 + b_cg * 8) * 2;

            uint32_t ar[4][4];
            uint32_t bhi[2][4], blo[2][4];   // [pair][frag]; pair p covers n-tiles 2p,2p+1

            // load B hi+lo (2 LDSM4 each) and A hi
#pragma unroll
            for (int pp = 0; pp < 2; pp++) {
                LDSM4(bhi[pp], bHi + boff + pp * 16 * (KROW * 2));
                LDSM4(blo[pp], bLo + boff + pp * 16 * (KROW * 2));
            }
#pragma unroll
            for (int mt = 0; mt < 4; mt++)
                LDSM4(ar[mt], aHi + aoff + mt * 16 * (KROW * 2));

            // pass 1: ahi x bhi   pass 2: ahi x blo (reuse ar)
#pragma unroll
            for (int mt = 0; mt < 4; mt++)
#pragma unroll
                for (int pp = 0; pp < 2; pp++) {
                    MMA(acc[mt][pp * 2],     ar[mt], (&bhi[pp][0]));
                    MMA(acc[mt][pp * 2 + 1], ar[mt], (&bhi[pp][2]));
                }
#pragma unroll
            for (int mt = 0; mt < 4; mt++)
#pragma unroll
                for (int pp = 0; pp < 2; pp++) {
                    MMA(acc[mt][pp * 2],     ar[mt], (&blo[pp][0]));
                    MMA(acc[mt][pp * 2 + 1], ar[mt], (&blo[pp][2]));
                }

            // pass 3: alo x bhi
#pragma unroll
            for (int mt = 0; mt < 4; mt++)
                LDSM4(ar[mt], aLo + aoff + mt * 16 * (KROW * 2));
#pragma unroll
            for (int mt = 0; mt < 4; mt++)
#pragma unroll
                for (int pp = 0; pp < 2; pp++) {
                    MMA(acc[mt][pp * 2],     ar[mt], (&bhi[pp][0]));
                    MMA(acc[mt][pp * 2 + 1], ar[mt], (&bhi[pp][2]));
                }
        }
        __syncthreads();
    }

    // epilogue
    int g = lane >> 2, t = lane & 3;
    int row0 = bm * 128 + wm * 64;
    int col0 = bn * 128 + wn * 32;
#pragma unroll
    for (int mt = 0; mt < 4; mt++) {
#pragma unroll
        for (int nt = 0; nt < 4; nt++) {
            float* p = g_x + (size_t)(row0 + mt * 16 + g) * E + col0 + nt * 8 + t * 2;
            *(float2*)p           = make_float2(acc[mt][nt][0], acc[mt][nt][1]);
            *(float2*)(p + 8 * E) = make_float2(acc[mt][nt][2], acc[mt][nt][3]);
        }
    }
}

// ---------------- pos-embed interp + bias + LayerNorm + scatter ------------
__global__ __launch_bounds__(256) void ln_kernel(const float* __restrict__ conv_b,
                                                 const float* __restrict__ pos_table,
                                                 const float* __restrict__ ln_w,
                                                 const float* __restrict__ ln_b,
                                                 float* __restrict__ out) {
    int gp = blockIdx.x;
    int im = 0;
#pragma unroll
    for (int i = 1; i < 6; i++) if (gp >= c_off[i]) im = i;
    int p = gp - c_off[im];
    int h = c_h[im], w = c_w[im];
    int py = p / w, px = p - py * w;

    float cy = (py + 0.5f) * (32.0f / (float)h) - 0.5f;
    cy = fminf(fmaxf(cy, 0.f), 31.f);
    float cx = (px + 0.5f) * (32.0f / (float)w) - 0.5f;
    cx = fminf(fmaxf(cx, 0.f), 31.f);
    int y0 = (int)cy; int y1 = min(y0 + 1, 31); float fy = cy - (float)y0;
    int x0 = (int)cx; int x1 = min(x0 + 1, 31); float fx = cx - (float)x0;

    const float* T00 = pos_table + (size_t)(1 + y0 * 32 + x0) * E;
    const float* T01 = pos_table + (size_t)(1 + y0 * 32 + x1) * E;
    const float* T10 = pos_table + (size_t)(1 + y1 * 32 + x0) * E;
    const float* T11 = pos_table + (size_t)(1 + y1 * 32 + x1) * E;
    float w00 = (1.f - fy) * (1.f - fx), w01 = (1.f - fy) * fx;
    float w10 = fy * (1.f - fx), w11 = fy * fx;

    int tid = threadIdx.x;
    float y[5];
    float s = 0.f, ss = 0.f;
#pragma unroll
    for (int i = 0; i < 5; i++) {
        int f = tid + i * 256;
        float v = g_x[(size_t)gp * E + f] + conv_b[f]
                + w00 * T00[f] + w01 * T01[f] + w10 * T10[f] + w11 * T11[f];
        y[i] = v;
        s += v;
        ss += v * v;
    }

    __shared__ float rs[8], rss[8];
#pragma unroll
    for (int o = 16; o > 0; o >>= 1) {
        s  += __shfl_xor_sync(0xffffffffu, s, o);
        ss += __shfl_xor_sync(0xffffffffu, ss, o);
    }
    if ((tid & 31) == 0) { rs[tid >> 5] = s; rss[tid >> 5] = ss; }
    __syncthreads();
    __shared__ float fm, finv;
    if (tid == 0) {
        float S = 0.f, SS = 0.f;
#pragma unroll
        for (int i = 0; i < 8; i++) { S += rs[i]; SS += rss[i]; }
        float m = S / (float)E;
        fm = m;
        finv = rsqrtf(SS / (float)E - m * m + 1e-5f);
    }
    __syncthreads();
    float m = fm, inv = finv;

    int row = c_bi[im] * MAXSEQ + c_s[im] + p;
    float* o = out + (size_t)row * E;
#pragma unroll
    for (int i = 0; i < 5; i++) {
        int f = tid + i * 256;
        o[f] = (y[i] - m) * inv * ln_w[f] + ln_b[f];
    }
}

// ---------------- zero uncovered emb rows: 4 rows per block ----------------
__global__ __launch_bounds__(256) void zero_kernel(float4* __restrict__ out) {
    int blk = blockIdx.x;              // 0..2559
    int b   = blk >> 9;                // 512 blocks per batch
    int r0  = (blk & 511) * 4;
    if (r0 + 4 <= c_cov[b]) return;    // fully covered by ln_kernel (cov % 4 == 0)
    float4* base = out + ((size_t)(b * MAXSEQ + r0) * E) / 4;
    int tid = threadIdx.x;
    float4 z = make_float4(0.f, 0.f, 0.f, 0.f);
#pragma unroll
    for (int i = 0; i < 5; i++) base[tid + i * 256] = z;   // 1280 float4 = 4 rows
}

// ---------------- mask fill: 4 rows per block, coalesced -------------------
__global__ __launch_bounds__(256) void mask_kernel(float4* __restrict__ mask) {
    int blk = blockIdx.x;              // 0..2559
    int b   = blk >> 9;
    int r0  = (blk & 511) * 4;         // all interval boundaries % 4 == 0
    const int* iv = c_iv[b];
    int lo = -1, hi = -1;
    if (r0 >= iv[0] && r0 < iv[1]) { lo = iv[0]; hi = iv[1]; }
    else if (iv[3] > iv[2] && r0 >= iv[2] && r0 < iv[3]) { lo = iv[2]; hi = iv[3]; }
    float4* base = mask + ((size_t)(b * MAXSEQ + r0) * MAXSEQ) / 4;
    int tid = threadIdx.x;
#pragma unroll
    for (int i = 0; i < 8; i++) {      // 2048 float4 = 4 rows of 512
        int fidx = tid + i * 256;
        int col  = (fidx & 511) * 4;
        float v = (col >= lo && col < hi) ? 1.f : 0.f;
        base[fidx] = make_float4(v, v, v, v);
    }
}

// ---------------- launch ----------------------------------------------------
extern "C" void kernel_launch(void* const* d_in, const int* in_sizes, int n_in,
                              void* d_out, int out_size) {
    Imgs imgs;
    for (int i = 0; i < 6; i++) imgs.p[i] = (const float*)d_in[i];
    const float* conv_w = (const float*)d_in[6];
    const float* conv_b = (const float*)d_in[7];
    const float* pos    = (const float*)d_in[8];
    const float* ln_w   = (const float*)d_in[9];
    const float* ln_b   = (const float*)d_in[10];

    float* out  = (float*)d_out;
    float* mask = out + (size_t)NB * MAXSEQ * E;

    // one-time host-side setup (created on the uncaptured correctness call)
    static cudaStream_t s2 = nullptr;
    static cudaEvent_t ev_fork = nullptr, ev_join = nullptr;
    if (!s2) {
        cudaStreamCreateWithFlags(&s2, cudaStreamNonBlocking);
        cudaEventCreateWithFlags(&ev_fork, cudaEventDisableTiming);
        cudaEventCreateWithFlags(&ev_join, cudaEventDisableTiming);
        cudaFuncSetAttribute(gemm_mma, cudaFuncAttributeMaxDynamicSharedMemorySize,
                             SMEM_TOTAL);
    }

    // fork: mask + zero run on s2, independent of the GEMM chain
    cudaEventRecord(ev_fork, 0);
    cudaStreamWaitEvent(s2, ev_fork, 0);
    mask_kernel<<<NB * MAXSEQ / 4, 256, 0, s2>>>((float4*)mask);
    zero_kernel<<<NB * MAXSEQ / 4, 256, 0, s2>>>((float4*)out);
    cudaEventRecord(ev_join, s2);

    a_conv_kernel<<<(NPATCH * KP + 255) / 256, 256>>>(imgs);
    b_conv_kernel<<<(E * KP + 255) / 256, 256>>>(conv_w);
    gemm_mma<<<dim3(E / 128, NPATCH / 128), 256, SMEM_TOTAL>>>();
    ln_kernel<<<NPATCH, 256>>>(conv_b, pos, ln_w, ln_b, out);

    // join
    cudaStreamWaitEvent(0, ev_join, 0);
}